// round 13
// baseline (speedup 1.0000x reference)
#include <cuda_runtime.h>

// Problem shape (fixed by reference):
//   z: (N=16, z_dim=64, H=32, W=32) fp32   -> zr: (L=4, P=16384, D=16)
//   e: (L=4, M=1024, D=16) fp32
//   log_sigma: (1,) fp32
// out = const - (1/(L*M)) * sum_{l,m} log( sum_p exp(alpha * d2[l,p,m]) )
//   alpha = -0.5*exp(-2*ls),  const = 32*(2*ls - 1) + log(16384)

#define LAT 4
#define MM  1024
#define PP  16384
#define DD  16
#define PS  8                 // P splits across blockIdx.y
#define CHUNK (PP/PS)         // 2048 points per block
#define TP  256               // points per shared tile

// Scratch (no allocations allowed in kernel_launch):
__device__ float g_zt [LAT*PP*DD];   // repacked z, [l][p][d] contiguous  (4 MB)
__device__ float g_zsq[LAT*PP];      // alpha*log2e * ||z_p||^2           (256 KB)
__device__ float g_part[PS*LAT*MM];  // partial exp-sums per P-split      (128 KB)

#define LOG2E 1.4426950408889634f

// ---------------------------------------------------------------------------
// Kernel 0: repack z into (l, p, d) contiguous layout + pre-scaled ||z||^2
// ---------------------------------------------------------------------------
__global__ void repack_kernel(const float* __restrict__ z,
                              const float* __restrict__ log_sigma) {
    int idx = blockIdx.x * blockDim.x + threadIdx.x;   // over LAT*PP = 65536
    if (idx >= LAT * PP) return;
    float ls = __ldg(log_sigma);
    float sc = -0.5f * expf(-2.f * ls) * LOG2E;        // alpha * log2(e)

    int l  = idx >> 14;          // idx / PP
    int p  = idx & (PP - 1);
    int n  = p >> 10;            // p / (H*W)
    int hw = p & 1023;

    // z[n][l*16 + d][hw], channel stride = H*W = 1024
    const float* zp = z + ((size_t)(n * 64 + l * 16)) * 1024 + hw;
    float v[DD];
    float sq = 0.f;
#pragma unroll
    for (int d = 0; d < DD; d++) {
        v[d] = zp[(size_t)d * 1024];
        sq = fmaf(v[d], v[d], sq);
    }
    float4* o = (float4*)(g_zt + (size_t)idx * DD);
    o[0] = make_float4(v[0],  v[1],  v[2],  v[3]);
    o[1] = make_float4(v[4],  v[5],  v[6],  v[7]);
    o[2] = make_float4(v[8],  v[9],  v[10], v[11]);
    o[3] = make_float4(v[12], v[13], v[14], v[15]);
    g_zsq[idx] = sc * sq;
}

// ---------------------------------------------------------------------------
// Kernel 1: fused distance + exp + partial sum over a P chunk.
// Block = 256 threads: lane (0..31) owns one m; 8 warps stripe the points.
// grid = (MM/32, PS, LAT)
// ---------------------------------------------------------------------------
__global__ __launch_bounds__(256) void lse_kernel(const float* __restrict__ e,
                                                  const float* __restrict__ log_sigma) {
    __shared__ float4 zs[TP * 4];    // 16 KB: TP points x 16 floats
    __shared__ float  zqs[TP];       // pre-scaled zsq
    __shared__ float  red[256];

    const int lane = threadIdx.x & 31;
    const int pg   = threadIdx.x >> 5;         // warp id 0..7
    const int l    = blockIdx.z;
    const int m    = blockIdx.x * 32 + lane;

    float ls = __ldg(log_sigma);
    float sc = -0.5f * expf(-2.f * ls) * LOG2E;

    // Codebook vector in registers
    const float4* ev = (const float4*)(e + ((size_t)l * MM + m) * DD);
    float4 e0 = ev[0], e1 = ev[1], e2 = ev[2], e3 = ev[3];
    float esq;
    {
        float a = fmaf(e0.x, e0.x, e0.y * e0.y);
        a = fmaf(e0.z, e0.z, a); a = fmaf(e0.w, e0.w, a);
        a = fmaf(e1.x, e1.x, a); a = fmaf(e1.y, e1.y, a);
        a = fmaf(e1.z, e1.z, a); a = fmaf(e1.w, e1.w, a);
        a = fmaf(e2.x, e2.x, a); a = fmaf(e2.y, e2.y, a);
        a = fmaf(e2.z, e2.z, a); a = fmaf(e2.w, e2.w, a);
        a = fmaf(e3.x, e3.x, a); a = fmaf(e3.y, e3.y, a);
        a = fmaf(e3.z, e3.z, a); a = fmaf(e3.w, e3.w, a);
        esq = a;
    }
    const float base_e = sc * esq;      // alpha*log2e*||e||^2
    const float n2     = -2.f * sc;     // -2*alpha*log2e

    float s = 0.f;
    const int p0 = blockIdx.y * CHUNK;
    const float4* ztl = (const float4*)g_zt + (size_t)(l * PP + p0) * 4;
    const float*  zql = g_zsq + (size_t)l * PP + p0;

    for (int t = 0; t < CHUNK; t += TP) {
        __syncthreads();
#pragma unroll
        for (int i = 0; i < (TP * 4) / 256; i++) {
            int j = threadIdx.x + i * 256;
            zs[j] = ztl[(size_t)t * 4 + j];
        }
        zqs[threadIdx.x] = zql[t + threadIdx.x];   // TP == 256
        __syncthreads();

#pragma unroll 4
        for (int pp = pg; pp < TP; pp += 8) {
            float4 z0 = zs[pp * 4 + 0];
            float4 z1 = zs[pp * 4 + 1];
            float4 z2 = zs[pp * 4 + 2];
            float4 z3 = zs[pp * 4 + 3];
            float d0 = z0.x * e0.x, d1 = z0.y * e0.y, d2 = z0.z * e0.z, d3 = z0.w * e0.w;
            d0 = fmaf(z1.x, e1.x, d0); d1 = fmaf(z1.y, e1.y, d1);
            d2 = fmaf(z1.z, e1.z, d2); d3 = fmaf(z1.w, e1.w, d3);
            d0 = fmaf(z2.x, e2.x, d0); d1 = fmaf(z2.y, e2.y, d1);
            d2 = fmaf(z2.z, e2.z, d2); d3 = fmaf(z2.w, e2.w, d3);
            d0 = fmaf(z3.x, e3.x, d0); d1 = fmaf(z3.y, e3.y, d1);
            d2 = fmaf(z3.z, e3.z, d2); d3 = fmaf(z3.w, e3.w, d3);
            float dot = (d0 + d1) + (d2 + d3);
            // arg = alpha*log2e * (zsq + esq - 2*dot)
            float arg = fmaf(n2, dot, zqs[pp] + base_e);
            float ex;
            asm("ex2.approx.ftz.f32 %0, %1;" : "=f"(ex) : "f"(arg));
            s += ex;
        }
    }

    // Reduce the 8 warp-stripes per m (red layout: [pg][lane])
    red[threadIdx.x] = s;
    __syncthreads();
    if (threadIdx.x < 128) red[threadIdx.x] += red[threadIdx.x + 128];
    __syncthreads();
    if (threadIdx.x < 64)  red[threadIdx.x] += red[threadIdx.x + 64];
    __syncthreads();
    if (threadIdx.x < 32) {
        float v = red[threadIdx.x] + red[threadIdx.x + 32];
        g_part[(size_t)blockIdx.y * (LAT * MM) + l * MM + m] = v;  // deterministic, no atomics
    }
}

// ---------------------------------------------------------------------------
// Kernel 2: combine P-splits, log, mean, constants
// ---------------------------------------------------------------------------
__global__ void finalize_kernel(const float* __restrict__ log_sigma,
                                float* __restrict__ out) {
    __shared__ float red[256];
    float acc = 0.f;
    for (int i = threadIdx.x; i < LAT * MM; i += 256) {
        float sum = 0.f;
#pragma unroll
        for (int ps = 0; ps < PS; ps++) sum += g_part[ps * (LAT * MM) + i];
        acc += logf(sum);
    }
    red[threadIdx.x] = acc;
    __syncthreads();
    for (int off = 128; off > 0; off >>= 1) {
        if (threadIdx.x < off) red[threadIdx.x] += red[threadIdx.x + off];
        __syncthreads();
    }
    if (threadIdx.x == 0) {
        float ls = log_sigma[0];
        // -mean(lse) + 0.5*z_dim*(2*ls - 1) + log(N*H*W)
        out[0] = -red[0] / (float)(LAT * MM) + 32.f * (2.f * ls - 1.f) + logf(16384.f);
    }
}

// ---------------------------------------------------------------------------
extern "C" void kernel_launch(void* const* d_in, const int* in_sizes, int n_in,
                              void* d_out, int out_size) {
    const float* z  = (const float*)d_in[0];
    const float* e  = (const float*)d_in[1];
    const float* ls = (const float*)d_in[2];
    float* out = (float*)d_out;

    repack_kernel<<<(LAT * PP + 255) / 256, 256>>>(z, ls);
    dim3 grid(MM / 32, PS, LAT);
    lse_kernel<<<grid, 256>>>(e, ls);
    finalize_kernel<<<1, 256>>>(ls, out);
}

// round 15
// speedup vs baseline: 1.0866x; 1.0866x over previous
#include <cuda_runtime.h>

// Problem shape (fixed by reference):
//   z: (N=16, z_dim=64, H=32, W=32) fp32   -> zr: (L=4, P=16384, D=16)
//   e: (L=4, M=1024, D=16) fp32
//   log_sigma: (1,) fp32
// out = const - (1/(L*M)) * sum_{l,m} log( sum_p exp(alpha * d2[l,p,m]) )

#define LAT 4
#define MM  1024
#define PP  16384
#define DD  16
#define PS  8                 // P splits across blockIdx.y
#define CHUNK (PP/PS)         // 2048 points per block
#define TP  512               // points per shared tile
#define NTILES (PP/TP)        // 32 global tiles per latent

// Scratch (no allocations allowed in kernel_launch):
// g_zt layout: [l][tile][d][TP]  (tile-transposed so 4 consecutive points of
// one dim are contiguous -> LDS.128 feeds two f32x2 operands)
__device__ float g_zt [LAT*PP*DD];   // 4 MB
__device__ float g_zsq[LAT*PP];      // alpha*log2e * ||z_p||^2  (256 KB)
__device__ float g_part[PS*LAT*MM];  // partial exp-sums per P-split

#define LOG2E 1.4426950408889634f

typedef unsigned long long ull;

__device__ __forceinline__ ull fma2(ull a, ull b, ull c) {
    ull d; asm("fma.rn.f32x2 %0,%1,%2,%3;" : "=l"(d) : "l"(a), "l"(b), "l"(c)); return d;
}
__device__ __forceinline__ ull add2(ull a, ull b) {
    ull d; asm("add.rn.f32x2 %0,%1,%2;" : "=l"(d) : "l"(a), "l"(b)); return d;
}
__device__ __forceinline__ ull dup2(float x) {
    ull d; asm("mov.b64 %0,{%1,%1};" : "=l"(d) : "f"(x)); return d;
}
__device__ __forceinline__ ull pack2(float lo, float hi) {
    ull d; asm("mov.b64 %0,{%1,%2};" : "=l"(d) : "f"(lo), "f"(hi)); return d;
}
__device__ __forceinline__ void unpack2(ull v, float& lo, float& hi) {
    asm("mov.b64 {%0,%1},%2;" : "=f"(lo), "=f"(hi) : "l"(v));
}
__device__ __forceinline__ float exp2_fast(float x) {
    float r; asm("ex2.approx.ftz.f32 %0,%1;" : "=f"(r) : "f"(x)); return r;
}

// ---------------------------------------------------------------------------
// Kernel 0: repack z into tile-transposed layout + pre-scaled ||z||^2
// ---------------------------------------------------------------------------
__global__ void repack_kernel(const float* __restrict__ z,
                              const float* __restrict__ log_sigma) {
    int idx = blockIdx.x * blockDim.x + threadIdx.x;   // over LAT*PP = 65536
    if (idx >= LAT * PP) return;
    float ls = __ldg(log_sigma);
    float sc = -0.5f * expf(-2.f * ls) * LOG2E;        // alpha * log2(e)

    int l  = idx >> 14;          // idx / PP
    int p  = idx & (PP - 1);
    int n  = p >> 10;            // p / (H*W)
    int hw = p & 1023;

    // z[n][l*16 + d][hw], channel stride = H*W = 1024
    const float* zp = z + ((size_t)(n * 64 + l * 16)) * 1024 + hw;
    float v[DD];
    float sq = 0.f;
#pragma unroll
    for (int d = 0; d < DD; d++) {
        v[d] = zp[(size_t)d * 1024];
        sq = fmaf(v[d], v[d], sq);
    }
    int tile = p / TP, pin = p % TP;
    float* o = g_zt + ((size_t)(l * NTILES + tile) * DD) * TP + pin;
#pragma unroll
    for (int d = 0; d < DD; d++) o[(size_t)d * TP] = v[d];
    g_zsq[idx] = sc * sq;
}

// ---------------------------------------------------------------------------
// Kernel 1: fused distance + exp + partial sum. f32x2 packed math, 4 pts/iter.
// Block = 256 threads: lane (0..31) owns one m; 8 warps stripe the points.
// grid = (MM/32, PS, LAT)
// ---------------------------------------------------------------------------
__global__ __launch_bounds__(256, 2) void lse_kernel(const float* __restrict__ e,
                                                     const float* __restrict__ log_sigma) {
    __shared__ __align__(16) float zs[DD * TP];   // 32 KB, [d][TP]
    __shared__ __align__(16) float zqs[TP];       // pre-scaled zsq (2 KB)
    __shared__ float red[256];

    const int tid  = threadIdx.x;
    const int lane = tid & 31;
    const int pg   = tid >> 5;          // warp id 0..7
    const int l    = blockIdx.z;
    const int m    = blockIdx.x * 32 + lane;

    float ls = __ldg(log_sigma);
    float sc = -0.5f * expf(-2.f * ls) * LOG2E;

    // Codebook vector: load, compute ||e||^2, duplicate-pack each component
    const float4* ev4 = (const float4*)(e + ((size_t)l * MM + m) * DD);
    float4 q0 = ev4[0], q1 = ev4[1], q2 = ev4[2], q3 = ev4[3];
    float evv[DD] = { q0.x,q0.y,q0.z,q0.w, q1.x,q1.y,q1.z,q1.w,
                      q2.x,q2.y,q2.z,q2.w, q3.x,q3.y,q3.z,q3.w };
    float esq = 0.f;
    ull ep[DD];
#pragma unroll
    for (int d = 0; d < DD; d++) {
        esq = fmaf(evv[d], evv[d], esq);
        ep[d] = dup2(evv[d]);
    }
    const float base_e = sc * esq;      // factored out: sum *= 2^base_e at the end
    const ull   n2p    = dup2(-2.f * sc);

    ull s01 = 0ull, s23 = 0ull;         // packed running sums (two zeros each)

    const int p0 = blockIdx.y * CHUNK;
    const float* zql = g_zsq + (size_t)l * PP + p0;

    for (int t = 0; t < CHUNK / TP; t++) {
        __syncthreads();
        // Fill tile: layout in global already matches [d][TP] -> linear copy
        const float4* src = (const float4*)(g_zt +
            ((size_t)(l * NTILES + (p0 / TP) + t) * DD) * TP);
        float4* dst = (float4*)zs;
#pragma unroll
        for (int i = 0; i < (DD * TP / 4) / 256; i++)
            dst[tid + i * 256] = src[tid + i * 256];
        zqs[tid]       = zql[t * TP + tid];
        zqs[tid + 256] = zql[t * TP + tid + 256];
        __syncthreads();

#pragma unroll 2
        for (int pp = pg * 4; pp < TP; pp += 32) {
            ull a0 = 0, a1 = 0, b0 = 0, b1 = 0;   // pair01 / pair23, 2 chains each
#pragma unroll
            for (int d = 0; d < DD; d++) {
                ulonglong2 v = *(const ulonglong2*)&zs[d * TP + pp];
                if (d & 1) { a1 = fma2(v.x, ep[d], a1); b1 = fma2(v.y, ep[d], b1); }
                else       { a0 = fma2(v.x, ep[d], a0); b0 = fma2(v.y, ep[d], b0); }
            }
            ull dotA = add2(a0, a1);
            ull dotB = add2(b0, b1);
            ulonglong2 zq = *(const ulonglong2*)&zqs[pp];
            ull argA = fma2(n2p, dotA, zq.x);     // alpha*log2e*(zsq - 2 dot)
            ull argB = fma2(n2p, dotB, zq.y);
            float x0, x1, x2, x3;
            unpack2(argA, x0, x1);
            unpack2(argB, x2, x3);
            s01 = add2(s01, pack2(exp2_fast(x0), exp2_fast(x1)));
            s23 = add2(s23, pack2(exp2_fast(x2), exp2_fast(x3)));
        }
    }

    float sa, sb, sc2, sd;
    unpack2(s01, sa, sb);
    unpack2(s23, sc2, sd);
    float s = (sa + sb) + (sc2 + sd);

    // Reduce the 8 warp-stripes per m
    red[tid] = s;
    __syncthreads();
    if (tid < 128) red[tid] += red[tid + 128];
    __syncthreads();
    if (tid < 64)  red[tid] += red[tid + 64];
    __syncthreads();
    if (tid < 32) {
        float v = red[tid] + red[tid + 32];
        v *= exp2_fast(base_e);           // re-apply factored ||e||^2 term
        g_part[(size_t)blockIdx.y * (LAT * MM) + l * MM + m] = v;
    }
}

// ---------------------------------------------------------------------------
// Kernel 2: combine P-splits, log, mean, constants
// ---------------------------------------------------------------------------
__global__ void finalize_kernel(const float* __restrict__ log_sigma,
                                float* __restrict__ out) {
    __shared__ float red[256];
    float acc = 0.f;
    for (int i = threadIdx.x; i < LAT * MM; i += 256) {
        float sum = 0.f;
#pragma unroll
        for (int ps = 0; ps < PS; ps++) sum += g_part[ps * (LAT * MM) + i];
        acc += logf(sum);
    }
    red[threadIdx.x] = acc;
    __syncthreads();
    for (int off = 128; off > 0; off >>= 1) {
        if (threadIdx.x < off) red[threadIdx.x] += red[threadIdx.x + off];
        __syncthreads();
    }
    if (threadIdx.x == 0) {
        float ls = log_sigma[0];
        out[0] = -red[0] / (float)(LAT * MM) + 32.f * (2.f * ls - 1.f) + logf(16384.f);
    }
}

// ---------------------------------------------------------------------------
extern "C" void kernel_launch(void* const* d_in, const int* in_sizes, int n_in,
                              void* d_out, int out_size) {
    const float* z  = (const float*)d_in[0];
    const float* e  = (const float*)d_in[1];
    const float* ls = (const float*)d_in[2];
    float* out = (float*)d_out;

    repack_kernel<<<(LAT * PP + 255) / 256, 256>>>(z, ls);
    dim3 grid(MM / 32, PS, LAT);
    lse_kernel<<<grid, 256>>>(e, ls);
    finalize_kernel<<<1, 256>>>(ls, out);
}

// round 16
// speedup vs baseline: 1.0924x; 1.0053x over previous
#include <cuda_runtime.h>

// Problem shape (fixed by reference):
//   z: (N=16, z_dim=64, H=32, W=32) fp32   -> zr: (L=4, P=16384, D=16)
//   e: (L=4, M=1024, D=16) fp32
//   log_sigma: (1,) fp32
// out = const - (1/(L*M)) * sum_{l,m} log( sum_p exp(alpha * d2[l,p,m]) )

#define LAT 4
#define MM  1024
#define PP  16384
#define DD  16
#define PS  8                 // P splits across blockIdx.y
#define CHUNK (PP/PS)         // 2048 points per block
#define TP  512               // points per shared tile
#define NTILES (PP/TP)        // 32 global tiles per latent

// Scratch (no allocations allowed in kernel_launch):
// g_zt layout: [l][tile][d][TP]  (tile-transposed so 4 consecutive points of
// one dim are contiguous -> LDS.128 feeds two f32x2 operands)
__device__ float g_zt [LAT*PP*DD];   // 4 MB
__device__ float g_zsq[LAT*PP];      // alpha*log2e * ||z_p||^2  (256 KB)
__device__ float g_part[PS*LAT*MM];  // partial exp-sums per P-split

#define LOG2E 1.4426950408889634f

typedef unsigned long long ull;

__device__ __forceinline__ ull fma2(ull a, ull b, ull c) {
    ull d; asm("fma.rn.f32x2 %0,%1,%2,%3;" : "=l"(d) : "l"(a), "l"(b), "l"(c)); return d;
}
__device__ __forceinline__ ull add2(ull a, ull b) {
    ull d; asm("add.rn.f32x2 %0,%1,%2;" : "=l"(d) : "l"(a), "l"(b)); return d;
}
__device__ __forceinline__ ull dup2(float x) {
    ull d; asm("mov.b64 %0,{%1,%1};" : "=l"(d) : "f"(x)); return d;
}
__device__ __forceinline__ ull pack2(float lo, float hi) {
    ull d; asm("mov.b64 %0,{%1,%2};" : "=l"(d) : "f"(lo), "f"(hi)); return d;
}
__device__ __forceinline__ void unpack2(ull v, float& lo, float& hi) {
    asm("mov.b64 {%0,%1},%2;" : "=f"(lo), "=f"(hi) : "l"(v));
}
__device__ __forceinline__ float exp2_fast(float x) {
    float r; asm("ex2.approx.ftz.f32 %0,%1;" : "=f"(r) : "f"(x)); return r;
}

// ---------------------------------------------------------------------------
// Kernel 0: repack z into tile-transposed layout + pre-scaled ||z||^2
// ---------------------------------------------------------------------------
__global__ void repack_kernel(const float* __restrict__ z,
                              const float* __restrict__ log_sigma) {
    int idx = blockIdx.x * blockDim.x + threadIdx.x;   // over LAT*PP = 65536
    if (idx >= LAT * PP) return;
    float ls = __ldg(log_sigma);
    float sc = -0.5f * expf(-2.f * ls) * LOG2E;        // alpha * log2(e)

    int l  = idx >> 14;          // idx / PP
    int p  = idx & (PP - 1);
    int n  = p >> 10;            // p / (H*W)
    int hw = p & 1023;

    // z[n][l*16 + d][hw], channel stride = H*W = 1024
    const float* zp = z + ((size_t)(n * 64 + l * 16)) * 1024 + hw;
    float v[DD];
    float sq = 0.f;
#pragma unroll
    for (int d = 0; d < DD; d++) {
        v[d] = zp[(size_t)d * 1024];
        sq = fmaf(v[d], v[d], sq);
    }
    int tile = p / TP, pin = p % TP;
    float* o = g_zt + ((size_t)(l * NTILES + tile) * DD) * TP + pin;
#pragma unroll
    for (int d = 0; d < DD; d++) o[(size_t)d * TP] = v[d];
    g_zsq[idx] = sc * sq;
}

// ---------------------------------------------------------------------------
// Kernel 1: fused distance + exp + partial sum. f32x2 packed math, 4 pts/iter.
// Block = 256 threads: lane (0..31) owns one m; 8 warps stripe the points.
// grid = (MM/32, PS, LAT)
// ---------------------------------------------------------------------------
__global__ __launch_bounds__(256, 2) void lse_kernel(const float* __restrict__ e,
                                                     const float* __restrict__ log_sigma) {
    __shared__ __align__(16) float zs[DD * TP];   // 32 KB, [d][TP]
    __shared__ __align__(16) float zqs[TP];       // pre-scaled zsq (2 KB)
    __shared__ float red[256];

    const int tid  = threadIdx.x;
    const int lane = tid & 31;
    const int pg   = tid >> 5;          // warp id 0..7
    const int l    = blockIdx.z;
    const int m    = blockIdx.x * 32 + lane;

    float ls = __ldg(log_sigma);
    float sc = -0.5f * expf(-2.f * ls) * LOG2E;

    // Codebook vector: load, compute ||e||^2, duplicate-pack each component
    const float4* ev4 = (const float4*)(e + ((size_t)l * MM + m) * DD);
    float4 q0 = ev4[0], q1 = ev4[1], q2 = ev4[2], q3 = ev4[3];
    float evv[DD] = { q0.x,q0.y,q0.z,q0.w, q1.x,q1.y,q1.z,q1.w,
                      q2.x,q2.y,q2.z,q2.w, q3.x,q3.y,q3.z,q3.w };
    float esq = 0.f;
    ull ep[DD];
#pragma unroll
    for (int d = 0; d < DD; d++) {
        esq = fmaf(evv[d], evv[d], esq);
        ep[d] = dup2(evv[d]);
    }
    const float base_e = sc * esq;      // factored out: sum *= 2^base_e at the end
    const ull   n2p    = dup2(-2.f * sc);

    ull s01 = 0ull, s23 = 0ull;         // packed running sums (two zeros each)

    const int p0 = blockIdx.y * CHUNK;
    const float* zql = g_zsq + (size_t)l * PP + p0;

    for (int t = 0; t < CHUNK / TP; t++) {
        __syncthreads();
        // Fill tile: layout in global already matches [d][TP] -> linear copy
        const float4* src = (const float4*)(g_zt +
            ((size_t)(l * NTILES + (p0 / TP) + t) * DD) * TP);
        float4* dst = (float4*)zs;
#pragma unroll
        for (int i = 0; i < (DD * TP / 4) / 256; i++)
            dst[tid + i * 256] = src[tid + i * 256];
        zqs[tid]       = zql[t * TP + tid];
        zqs[tid + 256] = zql[t * TP + tid + 256];
        __syncthreads();

#pragma unroll 2
        for (int pp = pg * 4; pp < TP; pp += 32) {
            ull a0 = 0, a1 = 0, b0 = 0, b1 = 0;   // pair01 / pair23, 2 chains each
#pragma unroll
            for (int d = 0; d < DD; d++) {
                ulonglong2 v = *(const ulonglong2*)&zs[d * TP + pp];
                if (d & 1) { a1 = fma2(v.x, ep[d], a1); b1 = fma2(v.y, ep[d], b1); }
                else       { a0 = fma2(v.x, ep[d], a0); b0 = fma2(v.y, ep[d], b0); }
            }
            ull dotA = add2(a0, a1);
            ull dotB = add2(b0, b1);
            ulonglong2 zq = *(const ulonglong2*)&zqs[pp];
            ull argA = fma2(n2p, dotA, zq.x);     // alpha*log2e*(zsq - 2 dot)
            ull argB = fma2(n2p, dotB, zq.y);
            float x0, x1, x2, x3;
            unpack2(argA, x0, x1);
            unpack2(argB, x2, x3);
            s01 = add2(s01, pack2(exp2_fast(x0), exp2_fast(x1)));
            s23 = add2(s23, pack2(exp2_fast(x2), exp2_fast(x3)));
        }
    }

    float sa, sb, sc2, sd;
    unpack2(s01, sa, sb);
    unpack2(s23, sc2, sd);
    float s = (sa + sb) + (sc2 + sd);

    // Reduce the 8 warp-stripes per m
    red[tid] = s;
    __syncthreads();
    if (tid < 128) red[tid] += red[tid + 128];
    __syncthreads();
    if (tid < 64)  red[tid] += red[tid + 64];
    __syncthreads();
    if (tid < 32) {
        float v = red[tid] + red[tid + 32];
        v *= exp2_fast(base_e);           // re-apply factored ||e||^2 term
        g_part[(size_t)blockIdx.y * (LAT * MM) + l * MM + m] = v;
    }
}

// ---------------------------------------------------------------------------
// Kernel 2: combine P-splits, log, mean, constants
// ---------------------------------------------------------------------------
__global__ void finalize_kernel(const float* __restrict__ log_sigma,
                                float* __restrict__ out) {
    __shared__ float red[256];
    float acc = 0.f;
    for (int i = threadIdx.x; i < LAT * MM; i += 256) {
        float sum = 0.f;
#pragma unroll
        for (int ps = 0; ps < PS; ps++) sum += g_part[ps * (LAT * MM) + i];
        acc += logf(sum);
    }
    red[threadIdx.x] = acc;
    __syncthreads();
    for (int off = 128; off > 0; off >>= 1) {
        if (threadIdx.x < off) red[threadIdx.x] += red[threadIdx.x + off];
        __syncthreads();
    }
    if (threadIdx.x == 0) {
        float ls = log_sigma[0];
        out[0] = -red[0] / (float)(LAT * MM) + 32.f * (2.f * ls - 1.f) + logf(16384.f);
    }
}

// ---------------------------------------------------------------------------
extern "C" void kernel_launch(void* const* d_in, const int* in_sizes, int n_in,
                              void* d_out, int out_size) {
    const float* z  = (const float*)d_in[0];
    const float* e  = (const float*)d_in[1];
    const float* ls = (const float*)d_in[2];
    float* out = (float*)d_out;

    repack_kernel<<<(LAT * PP + 255) / 256, 256>>>(z, ls);
    dim3 grid(MM / 32, PS, LAT);
    lse_kernel<<<grid, 256>>>(e, ls);
    finalize_kernel<<<1, 256>>>(ls, out);
}